// round 1
// baseline (speedup 1.0000x reference)
#include <cuda_runtime.h>
#include <cuda_bf16.h>

#define NN 50000
#define EE 800000

// Scratch (static __device__ globals — allocation-free per harness rules)
__device__ float g_deg[NN];
__device__ float g_dinv[NN];
__device__ float g_agg[NN * 128];   // layer-1 aggregated input, later reused for t2 = h1@W2
__device__ float g_h1[NN * 256];    // relu(agg1 @ W1 + b1)

// ---------------------------------------------------------------------------
// Degree / normalization
// ---------------------------------------------------------------------------
__global__ void k_init_deg() {
    int i = blockIdx.x * blockDim.x + threadIdx.x;
    if (i < NN) g_deg[i] = 1.0f;   // self-loop contributes 1
}

__global__ void k_count(const int* __restrict__ dst) {
    int e = blockIdx.x * blockDim.x + threadIdx.x;
    if (e < EE) atomicAdd(&g_deg[dst[e]], 1.0f);
}

__global__ void k_dinv() {
    int i = blockIdx.x * blockDim.x + threadIdx.x;
    if (i < NN) g_dinv[i] = rsqrtf(g_deg[i]);
}

// ---------------------------------------------------------------------------
// Self-loop term: out[i][c] = feat[i][c] * dinv[i]^2   (128 cols, float4)
// Also serves as the accumulator initializer (no memset needed).
// ---------------------------------------------------------------------------
__global__ void k_self(const float* __restrict__ feat, float* __restrict__ out) {
    int idx = blockIdx.x * blockDim.x + threadIdx.x;   // [0, NN*32)
    if (idx >= NN * 32) return;
    int node = idx >> 5;
    float d = g_dinv[node];
    float s = d * d;
    float4 v = reinterpret_cast<const float4*>(feat)[idx];
    v.x *= s; v.y *= s; v.z *= s; v.w *= s;
    reinterpret_cast<float4*>(out)[idx] = v;
}

// ---------------------------------------------------------------------------
// Edge aggregation: one warp per edge, 128 cols = 32 lanes x float4.
// out[dst] += feat[src] * (dinv[src]*dinv[dst])  via fp32 global atomics.
// ---------------------------------------------------------------------------
__global__ void k_agg(const int* __restrict__ srcI, const int* __restrict__ dstI,
                      const float* __restrict__ feat, float* __restrict__ out) {
    int e = blockIdx.x * (blockDim.x >> 5) + (threadIdx.x >> 5);
    if (e >= EE) return;
    int lane = threadIdx.x & 31;
    int s = srcI[e];
    int d = dstI[e];
    float norm = g_dinv[s] * g_dinv[d];
    float4 v = reinterpret_cast<const float4*>(feat)[s * 32 + lane];
    float* o = out + (size_t)d * 128 + lane * 4;
    atomicAdd(o + 0, v.x * norm);
    atomicAdd(o + 1, v.y * norm);
    atomicAdd(o + 2, v.z * norm);
    atomicAdd(o + 3, v.w * norm);
}

// ---------------------------------------------------------------------------
// Tiled fp32 SGEMM: C[M,N] = A[M,K] @ B[K,N]  (row-major), optional bias+relu.
// BM=BN=128, BK=16, 256 threads, 8x8 register tile per thread.
// N and K are multiples of 16/128 here; only M needs guards.
// ---------------------------------------------------------------------------
template <bool RELU_BIAS>
__global__ void sgemm(const float* __restrict__ A, const float* __restrict__ B,
                      const float* __restrict__ bias, float* __restrict__ C,
                      int M, int N, int K) {
    constexpr int BM = 128, BN = 128, BK = 16;
    __shared__ float As[BK][BM];
    __shared__ float Bs[BK][BN];

    int tid = threadIdx.x;          // 0..255
    int tr  = tid >> 4;             // 0..15  (row group)
    int tc  = tid & 15;             // 0..15  (col group)
    int rowBase = blockIdx.y * BM;
    int colBase = blockIdx.x * BN;

    float acc[8][8] = {};

    for (int kt = 0; kt < K; kt += BK) {
        // Load A tile (128x16) as 512 float4, transposed into As[k][m]
#pragma unroll
        for (int t = 0; t < 2; t++) {
            int idx = tid + t * 256;        // 0..511
            int r   = idx >> 2;             // 0..127
            int c4  = idx & 3;              // which float4 in the 16-wide row
            int row = rowBase + r;
            float4 v = make_float4(0.f, 0.f, 0.f, 0.f);
            if (row < M)
                v = *reinterpret_cast<const float4*>(A + (size_t)row * K + kt + c4 * 4);
            As[c4 * 4 + 0][r] = v.x;
            As[c4 * 4 + 1][r] = v.y;
            As[c4 * 4 + 2][r] = v.z;
            As[c4 * 4 + 3][r] = v.w;
        }
        // Load B tile (16x128) as 512 float4
#pragma unroll
        for (int t = 0; t < 2; t++) {
            int idx = tid + t * 256;
            int r   = idx >> 5;             // 0..15
            int c4  = idx & 31;             // 0..31
            float4 v = *reinterpret_cast<const float4*>(
                B + (size_t)(kt + r) * N + colBase + c4 * 4);
            *reinterpret_cast<float4*>(&Bs[r][c4 * 4]) = v;
        }
        __syncthreads();

#pragma unroll
        for (int k = 0; k < BK; k++) {
            float ra[8], rb[8];
#pragma unroll
            for (int i = 0; i < 8; i++) ra[i] = As[k][tr * 8 + i];
#pragma unroll
            for (int j = 0; j < 8; j++) rb[j] = Bs[k][tc * 8 + j];
#pragma unroll
            for (int i = 0; i < 8; i++)
#pragma unroll
                for (int j = 0; j < 8; j++)
                    acc[i][j] += ra[i] * rb[j];
        }
        __syncthreads();
    }

#pragma unroll
    for (int i = 0; i < 8; i++) {
        int row = rowBase + tr * 8 + i;
        if (row >= M) continue;
#pragma unroll
        for (int j = 0; j < 8; j += 4) {
            int col = colBase + tc * 8 + j;
            float4 v;
            v.x = acc[i][j + 0];
            v.y = acc[i][j + 1];
            v.z = acc[i][j + 2];
            v.w = acc[i][j + 3];
            if (RELU_BIAS) {
                v.x = fmaxf(v.x + bias[col + 0], 0.f);
                v.y = fmaxf(v.y + bias[col + 1], 0.f);
                v.z = fmaxf(v.z + bias[col + 2], 0.f);
                v.w = fmaxf(v.w + bias[col + 3], 0.f);
            }
            *reinterpret_cast<float4*>(C + (size_t)row * N + col) = v;
        }
    }
}

// ---------------------------------------------------------------------------
// Final epilogue for layer 2: out = relu(out + b2)   (in place, 128 cols)
// ---------------------------------------------------------------------------
__global__ void k_final(float* __restrict__ out, const float* __restrict__ b) {
    int idx = blockIdx.x * blockDim.x + threadIdx.x;   // [0, NN*32)
    if (idx >= NN * 32) return;
    int c4 = idx & 31;
    float4 v  = reinterpret_cast<float4*>(out)[idx];
    float4 bb = reinterpret_cast<const float4*>(b)[c4];
    v.x = fmaxf(v.x + bb.x, 0.f);
    v.y = fmaxf(v.y + bb.y, 0.f);
    v.z = fmaxf(v.z + bb.z, 0.f);
    v.w = fmaxf(v.w + bb.w, 0.f);
    reinterpret_cast<float4*>(out)[idx] = v;
}

// ---------------------------------------------------------------------------
// Launch
// ---------------------------------------------------------------------------
extern "C" void kernel_launch(void* const* d_in, const int* in_sizes, int n_in,
                              void* d_out, int out_size) {
    const float* x  = (const float*)d_in[0];
    const int*   ei = (const int*)d_in[1];     // [2, E]
    const float* W1 = (const float*)d_in[2];   // [128, 256]
    const float* b1 = (const float*)d_in[3];   // [256]
    const float* W2 = (const float*)d_in[4];   // [256, 128]
    const float* b2 = (const float*)d_in[5];   // [128]
    float* out = (float*)d_out;                // [NN, 128]

    const int* srcI = ei;
    const int* dstI = ei + EE;

    float *agg, *h1;
    cudaGetSymbolAddress((void**)&agg, g_agg);
    cudaGetSymbolAddress((void**)&h1,  g_h1);

    // Normalization (shared by both layers)
    k_init_deg<<<(NN + 255) / 256, 256>>>();
    k_count<<<(EE + 255) / 256, 256>>>(dstI);
    k_dinv<<<(NN + 255) / 256, 256>>>();

    // Layer 1: aggregate x (128 cols) FIRST, then GEMM+bias+relu.
    // (A(XW) == (AX)W — halves aggregation traffic vs reference order.)
    k_self<<<(NN * 32 + 255) / 256, 256>>>(x, agg);
    k_agg<<<EE / 8, 256>>>(srcI, dstI, x, agg);
    {
        dim3 grid(256 / 128, (NN + 127) / 128);
        sgemm<true><<<grid, 256>>>(agg, W1, b1, h1, NN, 256, 128);
    }

    // Layer 2: GEMM first (256->128), then aggregate (128 cols), then bias+relu.
    {
        dim3 grid(128 / 128, (NN + 127) / 128);
        sgemm<false><<<grid, 256>>>(h1, W2, nullptr, agg, NN, 128, 256);
    }
    k_self<<<(NN * 32 + 255) / 256, 256>>>(agg, out);
    k_agg<<<EE / 8, 256>>>(srcI, dstI, agg, out);
    k_final<<<(NN * 32 + 255) / 256, 256>>>(out, b2);
}

// round 2
// speedup vs baseline: 2.0257x; 2.0257x over previous
#include <cuda_runtime.h>
#include <cuda_bf16.h>

#define NN 50000
#define EE 800000

// Scratch (static __device__ globals — allocation-free per harness rules)
__device__ int   g_cnt[NN];          // in-degree (excl. self-loop)
__device__ int   g_rowptr[NN + 1];   // CSR row pointers (by dst)
__device__ int   g_cursor[NN];       // scatter cursors
__device__ int   g_src[EE];          // CSR column indices (src node per edge)
__device__ float g_dinv[NN];
__device__ float g_agg[NN * 128];    // layer-1 aggregated input; reused for t2 = h1@W2
__device__ float g_h1[NN * 256];     // relu(agg1 @ W1 + b1)

// ---------------------------------------------------------------------------
// CSR build: histogram -> dinv -> scan -> scatter
// ---------------------------------------------------------------------------
__global__ void k_zero() {
    int i = blockIdx.x * blockDim.x + threadIdx.x;
    if (i < NN) g_cnt[i] = 0;
}

__global__ void k_hist(const int* __restrict__ dst) {
    int e = blockIdx.x * blockDim.x + threadIdx.x;
    if (e < EE) atomicAdd(&g_cnt[dst[e]], 1);
}

__global__ void k_dinv() {
    int i = blockIdx.x * blockDim.x + threadIdx.x;
    if (i < NN) g_dinv[i] = rsqrtf((float)g_cnt[i] + 1.0f);  // +1 = self-loop
}

// Single-block exclusive scan over g_cnt -> g_rowptr / g_cursor
__global__ void k_scan() {
    __shared__ int warpsum[32];
    __shared__ int s_carry;
    int tid  = threadIdx.x;          // 0..1023
    int lane = tid & 31;
    int wid  = tid >> 5;
    if (tid == 0) s_carry = 0;
    __syncthreads();

    for (int base = 0; base < NN; base += 1024) {
        int i = base + tid;
        int v = (i < NN) ? g_cnt[i] : 0;
        // warp inclusive scan
        int x = v;
#pragma unroll
        for (int o = 1; o < 32; o <<= 1) {
            int y = __shfl_up_sync(0xFFFFFFFFu, x, o);
            if (lane >= o) x += y;
        }
        if (lane == 31) warpsum[wid] = x;
        __syncthreads();
        if (wid == 0) {
            int w = warpsum[lane];
#pragma unroll
            for (int o = 1; o < 32; o <<= 1) {
                int y = __shfl_up_sync(0xFFFFFFFFu, w, o);
                if (lane >= o) w += y;
            }
            warpsum[lane] = w;
        }
        __syncthreads();
        int carry   = s_carry;
        int warpoff = wid ? warpsum[wid - 1] : 0;
        int excl    = carry + warpoff + x - v;
        if (i < NN) { g_rowptr[i] = excl; g_cursor[i] = excl; }
        int total = warpsum[31];
        __syncthreads();
        if (tid == 0) s_carry = carry + total;
        __syncthreads();
    }
    if (tid == 0) g_rowptr[NN] = s_carry;   // == EE
}

__global__ void k_scatter(const int* __restrict__ srcI, const int* __restrict__ dstI) {
    int e = blockIdx.x * blockDim.x + threadIdx.x;
    if (e >= EE) return;
    int pos = atomicAdd(&g_cursor[dstI[e]], 1);
    g_src[pos] = srcI[e];
}

// ---------------------------------------------------------------------------
// CSR aggregation: one warp per node, register accumulation, no atomics.
// out[n] = feat[n]*dinv[n]^2 + sum_{s->n} feat[s]*dinv[s]*dinv[n]
// FINAL: out = relu(out + bias)
// ---------------------------------------------------------------------------
template <bool FINAL>
__global__ void k_aggcsr(const float* __restrict__ feat, float* __restrict__ out,
                         const float* __restrict__ bias) {
    int n = blockIdx.x * (blockDim.x >> 5) + (threadIdx.x >> 5);
    if (n >= NN) return;
    int lane = threadIdx.x & 31;
    float dn = g_dinv[n];

    float4 acc = __ldg(reinterpret_cast<const float4*>(feat) + n * 32 + lane);
    float s2 = dn * dn;
    acc.x *= s2; acc.y *= s2; acc.z *= s2; acc.w *= s2;

    int beg = g_rowptr[n];
    int end = g_rowptr[n + 1];

    for (int j0 = beg; j0 < end; j0 += 32) {
        int j = j0 + lane;
        int myS = (j < end) ? g_src[j] : 0;
        float myD = (j < end) ? g_dinv[myS] : 0.0f;
        int cnt = min(32, end - j0);
        for (int t = 0; t < cnt; t++) {
            int   s    = __shfl_sync(0xFFFFFFFFu, myS, t);
            float norm = __shfl_sync(0xFFFFFFFFu, myD, t) * dn;
            float4 v = __ldg(reinterpret_cast<const float4*>(feat) + s * 32 + lane);
            acc.x += v.x * norm;
            acc.y += v.y * norm;
            acc.z += v.z * norm;
            acc.w += v.w * norm;
        }
    }

    if (FINAL) {
        float4 bb = __ldg(reinterpret_cast<const float4*>(bias) + lane);
        acc.x = fmaxf(acc.x + bb.x, 0.f);
        acc.y = fmaxf(acc.y + bb.y, 0.f);
        acc.z = fmaxf(acc.z + bb.z, 0.f);
        acc.w = fmaxf(acc.w + bb.w, 0.f);
    }
    reinterpret_cast<float4*>(out)[n * 32 + lane] = acc;
}

// ---------------------------------------------------------------------------
// Tiled fp32 SGEMM: C[M,N] = A[M,K] @ B[K,N]  (row-major), optional bias+relu.
// BM=BN=128, BK=16, 256 threads, 8x8 register tile per thread.
// ---------------------------------------------------------------------------
template <bool RELU_BIAS>
__global__ void sgemm(const float* __restrict__ A, const float* __restrict__ B,
                      const float* __restrict__ bias, float* __restrict__ C,
                      int M, int N, int K) {
    constexpr int BM = 128, BN = 128, BK = 16;
    __shared__ float As[BK][BM];
    __shared__ float Bs[BK][BN];

    int tid = threadIdx.x;          // 0..255
    int tr  = tid >> 4;             // 0..15
    int tc  = tid & 15;             // 0..15
    int rowBase = blockIdx.y * BM;
    int colBase = blockIdx.x * BN;

    float acc[8][8] = {};

    for (int kt = 0; kt < K; kt += BK) {
#pragma unroll
        for (int t = 0; t < 2; t++) {
            int idx = tid + t * 256;        // 0..511
            int r   = idx >> 2;             // 0..127
            int c4  = idx & 3;
            int row = rowBase + r;
            float4 v = make_float4(0.f, 0.f, 0.f, 0.f);
            if (row < M)
                v = *reinterpret_cast<const float4*>(A + (size_t)row * K + kt + c4 * 4);
            As[c4 * 4 + 0][r] = v.x;
            As[c4 * 4 + 1][r] = v.y;
            As[c4 * 4 + 2][r] = v.z;
            As[c4 * 4 + 3][r] = v.w;
        }
#pragma unroll
        for (int t = 0; t < 2; t++) {
            int idx = tid + t * 256;
            int r   = idx >> 5;
            int c4  = idx & 31;
            float4 v = *reinterpret_cast<const float4*>(
                B + (size_t)(kt + r) * N + colBase + c4 * 4);
            *reinterpret_cast<float4*>(&Bs[r][c4 * 4]) = v;
        }
        __syncthreads();

#pragma unroll
        for (int k = 0; k < BK; k++) {
            float ra[8], rb[8];
#pragma unroll
            for (int i = 0; i < 8; i++) ra[i] = As[k][tr * 8 + i];
#pragma unroll
            for (int j = 0; j < 8; j++) rb[j] = Bs[k][tc * 8 + j];
#pragma unroll
            for (int i = 0; i < 8; i++)
#pragma unroll
                for (int j = 0; j < 8; j++)
                    acc[i][j] += ra[i] * rb[j];
        }
        __syncthreads();
    }

#pragma unroll
    for (int i = 0; i < 8; i++) {
        int row = rowBase + tr * 8 + i;
        if (row >= M) continue;
#pragma unroll
        for (int j = 0; j < 8; j += 4) {
            int col = colBase + tc * 8 + j;
            float4 v;
            v.x = acc[i][j + 0];
            v.y = acc[i][j + 1];
            v.z = acc[i][j + 2];
            v.w = acc[i][j + 3];
            if (RELU_BIAS) {
                v.x = fmaxf(v.x + bias[col + 0], 0.f);
                v.y = fmaxf(v.y + bias[col + 1], 0.f);
                v.z = fmaxf(v.z + bias[col + 2], 0.f);
                v.w = fmaxf(v.w + bias[col + 3], 0.f);
            }
            *reinterpret_cast<float4*>(C + (size_t)row * N + col) = v;
        }
    }
}

// ---------------------------------------------------------------------------
// Launch
// ---------------------------------------------------------------------------
extern "C" void kernel_launch(void* const* d_in, const int* in_sizes, int n_in,
                              void* d_out, int out_size) {
    const float* x  = (const float*)d_in[0];
    const int*   ei = (const int*)d_in[1];     // [2, E]
    const float* W1 = (const float*)d_in[2];   // [128, 256]
    const float* b1 = (const float*)d_in[3];   // [256]
    const float* W2 = (const float*)d_in[4];   // [256, 128]
    const float* b2 = (const float*)d_in[5];   // [128]
    float* out = (float*)d_out;                // [NN, 128]

    const int* srcI = ei;
    const int* dstI = ei + EE;

    float *agg, *h1;
    cudaGetSymbolAddress((void**)&agg, g_agg);
    cudaGetSymbolAddress((void**)&h1,  g_h1);

    // CSR build (by destination) + normalization
    k_zero<<<(NN + 255) / 256, 256>>>();
    k_hist<<<(EE + 255) / 256, 256>>>(dstI);
    k_dinv<<<(NN + 255) / 256, 256>>>();
    k_scan<<<1, 1024>>>();
    k_scatter<<<(EE + 255) / 256, 256>>>(srcI, dstI);

    // Layer 1: aggregate x (128 cols) FIRST, then GEMM+bias+relu.
    // (A(XW) == (AX)W — halves aggregation traffic vs reference order.)
    k_aggcsr<false><<<(NN + 7) / 8, 256>>>(x, agg, nullptr);
    {
        dim3 grid(256 / 128, (NN + 127) / 128);
        sgemm<true><<<grid, 256>>>(agg, W1, b1, h1, NN, 256, 128);
    }

    // Layer 2: GEMM first (256->128), then aggregate + bias + relu (fused).
    {
        dim3 grid(128 / 128, (NN + 127) / 128);
        sgemm<false><<<grid, 256>>>(h1, W2, nullptr, agg, NN, 128, 256);
    }
    k_aggcsr<true><<<(NN + 7) / 8, 256>>>(agg, out, b2);
}